// round 13
// baseline (speedup 1.0000x reference)
#include <cuda_runtime.h>
#include <cstdint>

// Skinny GEMM via mma.sync tf32, cp.async.bulk (TMA-engine) staged pipeline.
// C[65536,40] = embs[65536,1024] @ W^T, W = [W_status(5); W_flight(30); 0pad]
// R13 thesis: every LDG/cp.async variant equilibrates at ~13 B/cyc/SM because
// the per-SM L1tex outstanding-miss capacity (~64 lines ~ 8KB) caps in-flight
// bytes. cp.async.bulk is serviced by the TMA engine with its own tracking ->
// 2-stage CTA pipeline holds ~96KB/SM in flight. Per-row 128B bulk ops (rows
// are 4KB strided), mbarrier complete_tx, try_wait.parity consumers.
// Rows stored permuted (pi=[0,4,1,5,2,6,3,7] per 8-row group, stride 36
// floats) -> conflict-free LDS.128 fragments.
// Raw fp32 bits as tf32 (RZ truncate), bias corrected in epilogue.

#define EMB    1024
#define NS     5
#define NF     30
#define NL     35
#define OUTC   63
#define BM     128
#define NTH    128
#define NCH    32            // chunks of 32 K-floats (128B per row)
#define STR    36            // smem row stride in floats (144B, 16B aligned)
#define LSTR   41

#define SA_BYTES (128 * STR * 4)          // 18432
#define SB_BYTES (40 * STR * 4)           // 5760
#define STG_BYTES (SA_BYTES + SB_BYTES)   // 24192
#define MB_OFF   (2 * STG_BYTES)          // 48384
#define SMEM_TOTAL (MB_OFF + 64)
#define TXB      ((128 + 35) * 128)       // 20864 bytes per stage refill

__device__ __forceinline__ void mma8(float* c, const uint32_t* a, const uint32_t* b) {
    asm volatile(
        "mma.sync.aligned.m16n8k8.row.col.f32.tf32.tf32.f32 "
        "{%0,%1,%2,%3}, {%4,%5,%6,%7}, {%8,%9}, {%0,%1,%2,%3};"
        : "+f"(c[0]), "+f"(c[1]), "+f"(c[2]), "+f"(c[3])
        : "r"(a[0]), "r"(a[1]), "r"(a[2]), "r"(a[3]), "r"(b[0]), "r"(b[1]));
}
__device__ __forceinline__ void bulk128(uint32_t dst, const float* src, uint32_t mbar) {
    asm volatile(
        "cp.async.bulk.shared::cluster.global.mbarrier::complete_tx::bytes "
        "[%0], [%1], 128, [%2];"
        :: "r"(dst), "l"(src), "r"(mbar) : "memory");
}
__device__ __forceinline__ void mbar_init(uint32_t a, uint32_t cnt) {
    asm volatile("mbarrier.init.shared.b64 [%0], %1;" :: "r"(a), "r"(cnt) : "memory");
}
__device__ __forceinline__ void mbar_expect(uint32_t a, uint32_t bytes) {
    asm volatile("mbarrier.arrive.expect_tx.shared.b64 _, [%0], %1;"
                 :: "r"(a), "r"(bytes) : "memory");
}
__device__ __forceinline__ void mbar_wait(uint32_t a, uint32_t par) {
    asm volatile(
        "{\n\t.reg .pred P;\n"
        "WL_%=:\n\t"
        "mbarrier.try_wait.parity.acquire.cta.shared::cta.b64 P, [%0], %1, 0x989680;\n\t"
        "@P bra.uni WD_%=;\n\t"
        "bra.uni WL_%=;\n"
        "WD_%=:\n\t}"
        :: "r"(a), "r"(par) : "memory");
}
__device__ __forceinline__ uint4 lds128(uint32_t a) {
    uint4 v;
    asm volatile("ld.shared.v4.u32 {%0,%1,%2,%3}, [%4];"
                 : "=r"(v.x), "=r"(v.y), "=r"(v.z), "=r"(v.w) : "r"(a));
    return v;
}

extern __shared__ __align__(16) char smemraw[];

__global__ __launch_bounds__(NTH, 4) void aux2_bulk_kernel(
    const float* __restrict__ embs,
    const float* __restrict__ W_status,
    const float* __restrict__ b_status,
    const float* __restrict__ W_flight,
    const float* __restrict__ b_flight,
    float* __restrict__ out,
    int ntok)
{
    const int tid  = threadIdx.x;
    const int wid  = tid >> 5;
    const int lane = tid & 31;
    const int g    = lane >> 2;     // 0..7
    const int t    = lane & 3;      // 0..3
    const int sg   = (g >> 1) | ((g & 1) << 2);   // pi permutation of g
    const long tok0 = (long)blockIdx.x * BM;

    const uint32_t sbase = (uint32_t)__cvta_generic_to_shared(smemraw);

    // this thread's bulk-copy sources (row = tid)
    const float* asrc = embs + (tok0 + tid) * EMB;          // A row tid
    const float* bsrc = (tid < NS) ? (W_status + tid * EMB)
                       : (tid < NL) ? (W_flight + (tid - NS) * EMB) : nullptr;
    // permuted destination slots
    const uint32_t aslot = (uint32_t)((tid & ~7) | ((tid & 7) >> 1) | (((tid & 7) & 1) << 2));
    const uint32_t bslot = aslot;   // same formula, only used when tid < 35

    // zero both stages' B regions (pad rows 35..39 stay zero forever)
    for (int s = 0; s < 2; ++s)
        for (int i = tid; i < 40 * STR; i += NTH)
            *reinterpret_cast<float*>(smemraw + s * STG_BYTES + SA_BYTES + i * 4) = 0.0f;
    if (tid == 0) {
        mbar_init(sbase + MB_OFF, 1);
        mbar_init(sbase + MB_OFF + 8, 1);
    }
    __syncthreads();

    auto refill = [&](int s, int c) {
        uint32_t mb = sbase + MB_OFF + s * 8;
        if (tid == 0) mbar_expect(mb, TXB);
        // A: thread tid copies its row's 128B slice into permuted slot
        bulk128(sbase + (uint32_t)s * STG_BYTES + aslot * (STR * 4),
                asrc + c * 32, mb);
        // B: threads 0..34 copy weight rows
        if (tid < NL)
            bulk128(sbase + (uint32_t)s * STG_BYTES + SA_BYTES + bslot * (STR * 4),
                    bsrc + c * 32, mb);
    };

    refill(0, 0);
    refill(1, 1);

    float acc[2][5][4];
#pragma unroll
    for (int mt = 0; mt < 2; ++mt)
#pragma unroll
        for (int nt = 0; nt < 5; ++nt)
#pragma unroll
            for (int i = 0; i < 4; ++i) acc[mt][nt][i] = 0.0f;

#pragma unroll 1
    for (int c = 0; c < NCH; ++c) {
        const int s = c & 1;
        mbar_wait(sbase + MB_OFF + s * 8, (uint32_t)((c >> 1) & 1));

        const uint32_t Abase = sbase + (uint32_t)s * STG_BYTES;
        const uint32_t Bbase = Abase + SA_BYTES;

#pragma unroll
        for (int step = 0; step < 2; ++step) {          // 2 x k16 per chunk
            const uint32_t co = (uint32_t)(step * 64 + t * 16);
            uint4 a0[2], a1[2];
#pragma unroll
            for (int mt = 0; mt < 2; ++mt) {
                a0[mt] = lds128(Abase + (uint32_t)(wid * 32 + mt * 16 + sg) * (STR * 4) + co);
                a1[mt] = lds128(Abase + (uint32_t)(wid * 32 + mt * 16 + 8 + sg) * (STR * 4) + co);
            }
#pragma unroll
            for (int nt = 0; nt < 5; ++nt) {
                uint4 b = lds128(Bbase + (uint32_t)(nt * 8 + sg) * (STR * 4) + co);
                uint32_t bf0[2] = { b.x, b.y };
                uint32_t bf1[2] = { b.z, b.w };
#pragma unroll
                for (int mt = 0; mt < 2; ++mt) {
                    uint32_t af0[4] = { a0[mt].x, a1[mt].x, a0[mt].y, a1[mt].y };
                    uint32_t af1[4] = { a0[mt].z, a1[mt].z, a0[mt].w, a1[mt].w };
                    mma8(acc[mt][nt], af0, bf0);
                    mma8(acc[mt][nt], af1, bf1);
                }
            }
        }

        __syncthreads();               // all warps done reading stage s
        if (c + 2 < NCH) refill(s, c + 2);
    }
    __syncthreads();

    // ---- epilogue: fragments -> logits smem (alias stage memory) ----
    float* Ls = reinterpret_cast<float*>(smemraw);   // 128*41*4 = 21KB < 48KB
#pragma unroll
    for (int mt = 0; mt < 2; ++mt)
#pragma unroll
        for (int nt = 0; nt < 5; ++nt) {
            int r0 = wid * 32 + mt * 16 + g;
            int cc = nt * 8 + t * 2;
            if (cc < NL) {
                Ls[r0 * LSTR + cc]       = acc[mt][nt][0];
                Ls[(r0 + 8) * LSTR + cc] = acc[mt][nt][2];
            }
            if (cc + 1 < NL) {
                Ls[r0 * LSTR + cc + 1]       = acc[mt][nt][1];
                Ls[(r0 + 8) * LSTR + cc + 1] = acc[mt][nt][3];
            }
        }
    __syncthreads();

    // ---- per-thread dual softmax + store (thread tid = token) ----
    {
        const float corr = 1.000677f;   // tf32 RZ truncation bias compensation
        float sl[NS], fl[NF];
#pragma unroll
        for (int n = 0; n < NS; ++n) sl[n] = Ls[tid * LSTR + n] * corr + b_status[n];
#pragma unroll
        for (int n = 0; n < NF; ++n) fl[n] = Ls[tid * LSTR + NS + n] * corr + b_flight[n];

        float smax = sl[0];
#pragma unroll
        for (int n = 1; n < NS; ++n) smax = fmaxf(smax, sl[n]);
        float ssum = 0.f;
#pragma unroll
        for (int n = 0; n < NS; ++n) { sl[n] = __expf(sl[n] - smax); ssum += sl[n]; }
        float sinv = 1.f / ssum;
#pragma unroll
        for (int n = 0; n < NS; ++n) sl[n] *= sinv;

        float fm = fl[0];
#pragma unroll
        for (int n = 1; n < NF; ++n) fm = fmaxf(fm, fl[n]);
        float fsum = 0.f;
#pragma unroll
        for (int n = 0; n < NF; ++n) { fl[n] = __expf(fl[n] - fm); fsum += fl[n]; }
        float finv = 1.f / fsum;
#pragma unroll
        for (int n = 0; n < NF; ++n) fl[n] *= finv;

        const float book = sl[4], change = sl[3];
        long token = tok0 + tid;
        if (token < ntok) {
            float* op = out + token * (long)OUTC;
            op[0] = sl[0];
            op[1] = sl[2];
            op[2] = sl[1];
#pragma unroll
            for (int j = 0; j < NF; ++j) {
                op[3 + j]  = book   * fl[j];
                op[33 + j] = change * fl[j];
            }
        }
    }
}

extern "C" void kernel_launch(void* const* d_in, const int* in_sizes, int n_in,
                              void* d_out, int out_size) {
    const float* embs     = (const float*)d_in[0];
    const float* W_status = (const float*)d_in[1];
    const float* b_status = (const float*)d_in[2];
    const float* W_flight = (const float*)d_in[3];
    const float* b_flight = (const float*)d_in[4];
    float* out = (float*)d_out;

    cudaFuncSetAttribute(aux2_bulk_kernel,
                         cudaFuncAttributeMaxDynamicSharedMemorySize, SMEM_TOTAL);

    int ntok = in_sizes[0] / EMB;   // 65536
    int blocks = ntok / BM;         // 512
    aux2_bulk_kernel<<<blocks, NTH, SMEM_TOTAL>>>(embs, W_status, b_status,
                                                  W_flight, b_flight, out, ntok);
}

// round 14
// speedup vs baseline: 1.4844x; 1.4844x over previous
#include <cuda_runtime.h>
#include <cstdint>

// Skinny GEMM via mma.sync tf32: direct-LDG A + CTA-staged smem B.
// C[65536,40] = embs[65536,1024] @ W^T, W = [W_status(5); W_flight(30); 0pad]
// R14 thesis: runtime == per-SM L1tex wavefront budget. The old B-fragment
// LDGs touched 8 lines each (8 rows x 64B @4KB stride) = ~73k cyc/SM, half
// the kernel. Fix: B staged per k32 chunk into smem (line-dense cp.async,
// 3 buffers, staged 2 chunks ahead), fragments via cheap LDS.64. A keeps the
// proven direct-LDG path, issued BEFORE the barrier so latency hides there.
// Raw fp32 bits as tf32 (RZ truncate), bias corrected in epilogue.

#define EMB    1024
#define NS     5
#define NF     30
#define NL     35
#define OUTC   63
#define BM     128
#define NTH    128
#define NCH    32        // k32 chunks
#define STRB   40        // B smem row stride (floats); 160B -> 16B aligned
#define BUFF   1600      // floats per B buffer (40 rows * 40)
#define LSTR   41

__device__ __forceinline__ void mma8(float* c, const uint32_t* a, const uint32_t* b) {
    asm volatile(
        "mma.sync.aligned.m16n8k8.row.col.f32.tf32.tf32.f32 "
        "{%0,%1,%2,%3}, {%4,%5,%6,%7}, {%8,%9}, {%0,%1,%2,%3};"
        : "+f"(c[0]), "+f"(c[1]), "+f"(c[2]), "+f"(c[3])
        : "r"(a[0]), "r"(a[1]), "r"(a[2]), "r"(a[3]), "r"(b[0]), "r"(b[1]));
}
__device__ __forceinline__ void cp16(float* dst, const float* src) {
    unsigned s = (unsigned)__cvta_generic_to_shared(dst);
    asm volatile("cp.async.cg.shared.global [%0], [%1], 16;" :: "r"(s), "l"(src));
}
__device__ __forceinline__ void cp_commit() { asm volatile("cp.async.commit_group;"); }
template<int N> __device__ __forceinline__ void cp_wait() {
    asm volatile("cp.async.wait_group %0;" :: "n"(N));
}

__global__ __launch_bounds__(NTH, 4) void aux2_bsmem_kernel(
    const float* __restrict__ embs,
    const float* __restrict__ W_status,
    const float* __restrict__ b_status,
    const float* __restrict__ W_flight,
    const float* __restrict__ b_flight,
    float* __restrict__ out,
    int ntok)
{
    __shared__ __align__(16) float SU[5248];   // union: Bs[3][1600] | Ls[128*41]
    float* Bs = SU;

    const int tid  = threadIdx.x;
    const int wid  = tid >> 5;
    const int lane = tid & 31;
    const int g    = lane >> 2;     // 0..7
    const int t    = lane & 3;      // 0..3
    const long tokw = (long)blockIdx.x * BM + wid * 32;

    // A fragment base: rows tokw + r*8 + g, this lane's col 4t
    const float* Abase = embs + (tokw + g) * EMB + 4 * t;

    // B staging: line-dense (8 threads x 16B cover one row's 128B chunk)
    auto copyB = [&](int buf, int c) {
#pragma unroll
        for (int it = 0; it < 3; ++it) {
            int idx = it * NTH + tid;     // need 280 (35 rows x 8 units)
            int row = idx >> 3, u = idx & 7;
            if (row < NL) {
                const float* src = (row < NS) ? (W_status + row * EMB)
                                              : (W_flight + (row - NS) * EMB);
                cp16(Bs + buf * BUFF + row * STRB + u * 4, src + c * 32 + u * 4);
            }
        }
    };

    // zero pad rows 35..39 of all 3 buffers (never overwritten by staging)
    for (int i = tid; i < 3 * 5 * STRB; i += NTH) {
        int bf = i / (5 * STRB), rem = i % (5 * STRB);
        Bs[bf * BUFF + (NL + rem / STRB) * STRB + (rem % STRB)] = 0.0f;
    }
    __syncthreads();

    copyB(0, 0); cp_commit();
    copyB(1, 1); cp_commit();

    float acc[2][5][4];
#pragma unroll
    for (int mt = 0; mt < 2; ++mt)
#pragma unroll
        for (int nt = 0; nt < 5; ++nt)
#pragma unroll
            for (int i = 0; i < 4; ++i) acc[mt][nt][i] = 0.0f;

#pragma unroll 1
    for (int c = 0; c < NCH; ++c) {
        // A loads first: independent of B staging, latency hides under barrier
        uint4 a[2][4];
#pragma unroll
        for (int h = 0; h < 2; ++h)
#pragma unroll
            for (int r = 0; r < 4; ++r)
                a[h][r] = *(const uint4*)(Abase + r * 8 * EMB + (2 * c + h) * 16);

        cp_wait<1>();          // group c complete (this thread's copies)
        __syncthreads();       // all threads' copies of chunk c visible CTA-wide

        // stage chunk c+2 into buffer (c+2)%3 (== consumed at c-1, now safe)
        if (c + 2 < NCH) copyB((c + 2) % 3, c + 2);
        cp_commit();           // unconditional: uniform group accounting

        const float* Bp = Bs + (c % 3) * BUFF;
#pragma unroll
        for (int h = 0; h < 2; ++h) {
            uint32_t af0[2][4] = {
                { a[h][0].x, a[h][1].x, a[h][0].y, a[h][1].y },
                { a[h][2].x, a[h][3].x, a[h][2].y, a[h][3].y } };
            uint32_t af1[2][4] = {
                { a[h][0].z, a[h][1].z, a[h][0].w, a[h][1].w },
                { a[h][2].z, a[h][3].z, a[h][2].w, a[h][3].w } };
#pragma unroll
            for (int nt = 0; nt < 5; ++nt) {
                const float* brow = Bp + (nt * 8 + g) * STRB + 16 * h + 4 * t;
                uint2 w0 = *(const uint2*)(brow);       // cols {4t, 4t+1}
                uint2 w1 = *(const uint2*)(brow + 2);   // cols {4t+2, 4t+3}
                uint32_t bf0[2] = { w0.x, w0.y };
                uint32_t bf1[2] = { w1.x, w1.y };
#pragma unroll
                for (int mt = 0; mt < 2; ++mt) {
                    mma8(acc[mt][nt], af0[mt], bf0);
                    mma8(acc[mt][nt], af1[mt], bf1);
                }
            }
        }
    }

    cp_wait<0>();
    __syncthreads();          // B buffers dead; alias SU as logits

    // ---- epilogue: fragments -> logits smem ----
    float* Ls = SU;
#pragma unroll
    for (int mt = 0; mt < 2; ++mt)
#pragma unroll
        for (int nt = 0; nt < 5; ++nt) {
            int r0 = wid * 32 + mt * 16 + g;
            int cc = nt * 8 + t * 2;
            if (cc < NL) {
                Ls[r0 * LSTR + cc]       = acc[mt][nt][0];
                Ls[(r0 + 8) * LSTR + cc] = acc[mt][nt][2];
            }
            if (cc + 1 < NL) {
                Ls[r0 * LSTR + cc + 1]       = acc[mt][nt][1];
                Ls[(r0 + 8) * LSTR + cc + 1] = acc[mt][nt][3];
            }
        }
    __syncthreads();

    // ---- per-thread dual softmax + store (thread tid = token) ----
    {
        const float corr = 1.000677f;   // tf32 RZ truncation bias compensation
        float sl[NS], fl[NF];
#pragma unroll
        for (int n = 0; n < NS; ++n) sl[n] = Ls[tid * LSTR + n] * corr + b_status[n];
#pragma unroll
        for (int n = 0; n < NF; ++n) fl[n] = Ls[tid * LSTR + NS + n] * corr + b_flight[n];

        float smax = sl[0];
#pragma unroll
        for (int n = 1; n < NS; ++n) smax = fmaxf(smax, sl[n]);
        float ssum = 0.f;
#pragma unroll
        for (int n = 0; n < NS; ++n) { sl[n] = __expf(sl[n] - smax); ssum += sl[n]; }
        float sinv = 1.f / ssum;
#pragma unroll
        for (int n = 0; n < NS; ++n) sl[n] *= sinv;

        float fm = fl[0];
#pragma unroll
        for (int n = 1; n < NF; ++n) fm = fmaxf(fm, fl[n]);
        float fsum = 0.f;
#pragma unroll
        for (int n = 0; n < NF; ++n) { fl[n] = __expf(fl[n] - fm); fsum += fl[n]; }
        float finv = 1.f / fsum;
#pragma unroll
        for (int n = 0; n < NF; ++n) fl[n] *= finv;

        const float book = sl[4], change = sl[3];
        long token = (long)blockIdx.x * BM + tid;
        if (token < ntok) {
            float* op = out + token * (long)OUTC;
            op[0] = sl[0];
            op[1] = sl[2];
            op[2] = sl[1];
#pragma unroll
            for (int j = 0; j < NF; ++j) {
                op[3 + j]  = book   * fl[j];
                op[33 + j] = change * fl[j];
            }
        }
    }
}

extern "C" void kernel_launch(void* const* d_in, const int* in_sizes, int n_in,
                              void* d_out, int out_size) {
    const float* embs     = (const float*)d_in[0];
    const float* W_status = (const float*)d_in[1];
    const float* b_status = (const float*)d_in[2];
    const float* W_flight = (const float*)d_in[3];
    const float* b_flight = (const float*)d_in[4];
    float* out = (float*)d_out;

    int ntok = in_sizes[0] / EMB;   // 65536
    int blocks = ntok / BM;         // 512
    aux2_bsmem_kernel<<<blocks, NTH>>>(embs, W_status, b_status,
                                       W_flight, b_flight, out, ntok);
}